// round 12
// baseline (speedup 1.0000x reference)
#include <cuda_runtime.h>

typedef unsigned long long ull;

#define NTHREADS 256
#define ROWS_PER_CTA 32
#define GRID 1024            /* 32768 rows / 32 */

// shared layout (bytes)
#define OFF_XD   98304                 // after 2x48KB Wc double buffer
#define OFF_U    (OFF_XD + 64*34*8)    // 115712
#define OFF_V    (OFF_U + 3072*4)      // 128000
#define OFF_ADJJ (OFF_V + 192)         // 128192
#define OFF_RS   (OFF_ADJJ + 96)       // 128288
#define SMEM_BYTES (OFF_RS + 768 + 32) // 129088

// ---------------- device-global precomputed tables ----------------
__device__ float g_Wc[64 * 1536];   // [f][n][k]  = sum_h Wp[f, n*64+h] * W[h,k]
__device__ float g_u[64 * 48];      // [f][n], [f][24+n]
__device__ float g_v[48];
__device__ float g_bc[24 * 64];     // bc[n,k]

// ---------------- helpers ----------------
__device__ __forceinline__ ull packdup(float v) {
    ull r; asm("mov.b64 %0, {%1, %1};" : "=l"(r) : "f"(v)); return r;
}
#define FMA2(d, a_, b_, c_) \
    asm("fma.rn.f32x2 %0, %1, %2, %3;" : "=l"(d) : "l"(a_), "l"(b_), "l"(c_))
#define ADD2(d, a_, b_) \
    asm("add.rn.f32x2 %0, %1, %2;" : "=l"(d) : "l"(a_), "l"(b_))
#define PAIR_BAR(pid) \
    asm volatile("bar.sync %0, %1;" :: "r"((pid) + 1), "r"(64) : "memory")

__device__ __forceinline__ void cp16(unsigned smaddr, const void* g) {
    asm volatile("cp.async.cg.shared.global [%0], [%1], 16;" :: "r"(smaddr), "l"(g));
}

// ---------------- merged prep kernel ----------------
// blocks 0..1535  : Wc[f][n][k] + u reduction   (b = n*64 + f)
// blocks 1536..1559: bc[n][k] + v reduction
__global__ void prep(const float* __restrict__ Wp, const float* __restrict__ bp,
                     const float* __restrict__ W, const float* __restrict__ a) {
    int b = blockIdx.x;
    int k = threadIdx.x;          // 0..63
    float acc = 0.f;

    if (b < 1536) {
        int n = b >> 6, f = b & 63;
#pragma unroll 8
        for (int h = 0; h < 64; h++)
            acc = fmaf(Wp[f * 1536 + n * 64 + h], W[h * 64 + k], acc);
        g_Wc[f * 1536 + n * 64 + k] = acc;
    } else {
        int n = b - 1536;
#pragma unroll 8
        for (int h = 0; h < 64; h++)
            acc = fmaf(bp[n * 64 + h], W[h * 64 + k], acc);
        g_bc[n * 64 + k] = acc;
    }

    float p1 = acc * a[k];
    float p2 = acc * a[64 + k];
#pragma unroll
    for (int d = 16; d; d >>= 1) {
        p1 += __shfl_xor_sync(0xffffffffu, p1, d);
        p2 += __shfl_xor_sync(0xffffffffu, p2, d);
    }
    __shared__ float r1[2], r2[2];
    if ((k & 31) == 0) { r1[k >> 5] = p1; r2[k >> 5] = p2; }
    __syncthreads();
    if (k == 0) {
        if (b < 1536) {
            int n = b >> 6, f = b & 63;
            g_u[f * 48 + n]      = r1[0] + r1[1];
            g_u[f * 48 + 24 + n] = r2[0] + r2[1];
        } else {
            int n = b - 1536;
            g_v[n] = r1[0] + r1[1];
            g_v[24 + n] = r2[0] + r2[1];
        }
    }
}

// ---------------- main fused kernel ----------------
// 8 warps, 4 pairs. Pair p = w&3 owns rows 8p..8p+7.
// Warp p = low half (n 0..11), warp p+4 = high half (n 12..23).
__global__ __launch_bounds__(NTHREADS, 1)
void gat_main(const float* __restrict__ x, const int* __restrict__ adj,
              float* __restrict__ out) {
    extern __shared__ char smem[];
    float* s_wc   = (float*)smem;
    ull*   s_P    = (ull*)smem;                 // overlays Wc region in phase 2
    ull*   s_part = s_P + 4 * 600;              // park regions: 4 pairs x 2 x 768 ull
    ull*   s_xd   = (ull*)(smem + OFF_XD);      // 64 x 34 ull, {x,x} pairs [f][row]
    float* s_u    = (float*)(smem + OFF_U);
    float* s_v    = (float*)(smem + OFF_V);
    unsigned* s_adjJ = (unsigned*)(smem + OFF_ADJJ);
    float* s_rs   = (float*)(smem + OFF_RS);    // 4 pairs x 24

    const int tid  = threadIdx.x;
    const int lane = tid & 31;
    const int w    = tid >> 5;
    const int pair = w & 3;
    const int hi   = w >> 2;                    // 0 = n 0..11, 1 = n 12..23
    const int nbase = hi * 12;
    const int rowbase = blockIdx.x * ROWS_PER_CTA;

    const unsigned swc0 = (unsigned)__cvta_generic_to_shared(s_wc);

    // prologue: stage f-block 0 of Wc (8 f-rows, 48 KB) into buffer 0
    for (int c = tid; c < 3072; c += NTHREADS) cp16(swc0 + c * 16, g_Wc + c * 4);
    asm volatile("cp.async.commit_group;");

    // stage x as duplicated {x,x} pairs: s_xd[f*34 + r]
    for (int i = tid; i < ROWS_PER_CTA * 64; i += NTHREADS) {
        int r = i >> 6, f = i & 63;
        s_xd[f * 34 + r] = packdup(x[(rowbase + r) * 64 + f]);
    }
    for (int i = tid; i < 3072; i += NTHREADS) s_u[i] = g_u[i];
    if (tid < 48) s_v[tid] = g_v[tid];
    if (tid < 24) {
        unsigned b = 0;
        for (int i = 0; i < 24; i++) b |= (adj[i * 24 + tid] > 0 ? 1u : 0u) << i;
        s_adjJ[tid] = b;
    }

    // Wh accumulators: lane owns k = 2*lane, 2*lane+1; 8 rows x 12 n (this half)
    ull wh[8][12];
#pragma unroll
    for (int q = 0; q < 12; q++) {
        ull b = ((const ull*)g_bc)[(nbase + q) * 32 + lane];
#pragma unroll
        for (int r = 0; r < 8; r++) wh[r][q] = b;
    }

    __syncthreads();

    // ---------------- phase 1: Wh = x @ Wc + bc ----------------
    for (int fb = 0; fb < 8; fb++) {
        if (fb < 7) {
            unsigned dst = swc0 + (unsigned)(((fb + 1) & 1) * 49152);
            const float* src = g_Wc + (fb + 1) * 12288;
            for (int c = tid; c < 3072; c += NTHREADS) cp16(dst + c * 16, src + c * 4);
            asm volatile("cp.async.commit_group;");
            asm volatile("cp.async.wait_group 1;");
        } else {
            asm volatile("cp.async.wait_group 0;");
        }
        __syncthreads();

        const float* wct = s_wc + (fb & 1) * 12288;
#pragma unroll
        for (int ff = 0; ff < 8; ff++) {
            const ulonglong2* xp =
                (const ulonglong2*)(s_xd + (fb * 8 + ff) * 34 + 8 * pair);
            ulonglong2 xa = xp[0], xb = xp[1], xc = xp[2], xd = xp[3];
            const ull* wrow = ((const ull*)(wct + ff * 1536)) + nbase * 32 + lane;
#pragma unroll
            for (int g2 = 0; g2 < 3; g2++) {
                ull w2[4];
#pragma unroll
                for (int q = 0; q < 4; q++) w2[q] = wrow[(g2 * 4 + q) * 32];
#pragma unroll
                for (int q = 0; q < 4; q++) {
                    const int n = g2 * 4 + q;
                    FMA2(wh[0][n], w2[q], xa.x, wh[0][n]);
                    FMA2(wh[1][n], w2[q], xa.y, wh[1][n]);
                    FMA2(wh[2][n], w2[q], xb.x, wh[2][n]);
                    FMA2(wh[3][n], w2[q], xb.y, wh[3][n]);
                    FMA2(wh[4][n], w2[q], xc.x, wh[4][n]);
                    FMA2(wh[5][n], w2[q], xc.y, wh[5][n]);
                    FMA2(wh[6][n], w2[q], xd.x, wh[6][n]);
                    FMA2(wh[7][n], w2[q], xd.y, wh[7][n]);
                }
            }
        }
        __syncthreads();
    }

    // ---------------- phase 2: attention + aggregate ----------------
    const int ln = (lane < 24) ? lane : 0;
    const float* xdf = (const float*)s_xd;

    ull* Pw = s_P + pair * 600;                  // 24 x 25 ull per pair
    ull* Pk     = s_part + pair * 1536 + hi * 768;  // this warp's park region
    ull* PkLow  = s_part + pair * 1536;
    ull* PkHigh = s_part + pair * 1536 + 768;
    const float inv24 = 1.0f / 24.0f;

    for (int r = 0; r < 8; r++) {
        const int rl = 8 * pair + r;

        if (!hi) {
            // ---- f1/f2 for this row (lane = node n) ----
            float f1 = s_v[ln], f2 = s_v[24 + ln];
#pragma unroll 8
            for (int f = 0; f < 64; f++) {
                float xf = xdf[2 * (f * 34 + rl)];
                f1 = fmaf(xf, s_u[f * 48 + ln], f1);
                f2 = fmaf(xf, s_u[f * 48 + 24 + ln], f2);
            }
            // ---- stage A: unnormalized probs, lanes = i, loop j ----
            float sse = 0.f;
#pragma unroll 6
            for (int j = 0; j < 24; j++) {
                float f2j = __shfl_sync(0xffffffffu, f2, j);
                float e = f1 + f2j;
                e = (e > 0.f) ? e : 0.2f * e;          // LeakyReLU
                unsigned bits = s_adjJ[j];             // uniform
                float p = ((bits >> lane) & 1u) ? __expf(e) : 0.f;
                sse += p;
                if (lane < 24) Pw[lane * 25 + j] = packdup(p);
            }
            // rare: fully-masked row -> reference softmax is uniform
            bool bad = (lane < 24) && (sse == 0.f);
            if (__any_sync(0xffffffffu, bad)) {
                if (bad) {
                    for (int j = 0; j < 24; j++) Pw[lane * 25 + j] = packdup(1.f);
                    sse = 24.f;
                }
            }
            if (lane < 24) s_rs[pair * 24 + lane] = __fdividef(1.f, sse);
        }
        PAIR_BAR(pair);                                // probs ready

        // ---- stage B: BOTH warps compute their j-half partial, park in smem ----
        for (int i = 0; i < 24; i++) {
            const ull* Prow = Pw + i * 25 + nbase;
            ull hp0 = 0ULL, hp1 = 0ULL;
#pragma unroll
            for (int q = 0; q < 6; q++)  { FMA2(hp0, Prow[q], wh[r][q], hp0); }
#pragma unroll
            for (int q = 6; q < 12; q++) { FMA2(hp1, Prow[q], wh[r][q], hp1); }
            ull hp; ADD2(hp, hp0, hp1);
            Pk[i * 32 + lane] = hp;
        }
        PAIR_BAR(pair);                                // partials ready

        if (!hi) {
            // ---- combine: both halves, scale, ELU, mean ----
            float acc0 = 0.f, acc1 = 0.f;
            for (int i = 0; i < 24; i++) {
                ull pa = PkLow[i * 32 + lane];
                ull pb = PkHigh[i * 32 + lane];
                ull hp; ADD2(hp, pa, pb);
                float rsv = s_rs[pair * 24 + i];       // uniform
                float hx = __uint_as_float((unsigned)hp) * rsv;
                float hy = __uint_as_float((unsigned)(hp >> 32)) * rsv;
                acc0 += (hx > 0.f) ? hx : __expf(hx) - 1.f;   // ELU
                acc1 += (hy > 0.f) ? hy : __expf(hy) - 1.f;
            }
            const int row = rowbase + rl;
            float2 o; o.x = acc0 * inv24; o.y = acc1 * inv24;
            ((float2*)out)[row * 32 + lane] = o;
        }
        PAIR_BAR(pair);                                // protect Pw/Pk for next r
    }
}

// ---------------- launch ----------------
extern "C" void kernel_launch(void* const* d_in, const int* in_sizes, int n_in,
                              void* d_out, int out_size) {
    (void)in_sizes; (void)n_in; (void)out_size;
    const float* x   = (const float*)d_in[0];
    const int*   adj = (const int*)d_in[1];
    const float* Wp  = (const float*)d_in[2];
    const float* bp  = (const float*)d_in[3];
    const float* W   = (const float*)d_in[4];
    const float* a   = (const float*)d_in[5];
    float* out = (float*)d_out;

    cudaFuncSetAttribute(gat_main, cudaFuncAttributeMaxDynamicSharedMemorySize,
                         SMEM_BYTES);

    prep<<<1560, 64>>>(Wp, bp, W, a);
    gat_main<<<GRID, NTHREADS, SMEM_BYTES>>>(x, adj, out);
}

// round 13
// speedup vs baseline: 3.4367x; 3.4367x over previous
#include <cuda_runtime.h>

typedef unsigned long long ull;

#define NTHREADS 384
#define ROWS_PER_CTA 24
#define GRID 1366            /* ceil(32768 / 24) */
#define TOTAL_ROWS 32768

// shared layout (bytes)
#define OFF_XD   98304                 // after 2x48KB Wc double buffer
#define OFF_U    (OFF_XD + 64*26*8)    // 111616
#define OFF_V    (OFF_U + 3072*4)      // 123904
#define OFF_ADJJ (OFF_V + 192)         // 124096
#define OFF_SSE  (OFF_ADJJ + 96)       // 124192
#define OFF_RS   (OFF_SSE + 6*64*4)    // 125728
#define OFF_BAD  (OFF_RS + 6*24*4)     // 126304
#define SMEM_BYTES (OFF_BAD + 32)      // 126336

// ---------------- device-global precomputed tables ----------------
__device__ float g_Wc[64 * 1536];   // [f][n][k]  = sum_h Wp[f, n*64+h] * W[h,k]
__device__ float g_u[64 * 48];      // [f][n], [f][24+n]
__device__ float g_v[48];
__device__ float g_bc[24 * 64];     // bc[n,k]

// ---------------- helpers ----------------
__device__ __forceinline__ ull packdup(float v) {
    ull r; asm("mov.b64 %0, {%1, %1};" : "=l"(r) : "f"(v)); return r;
}
#define FMA2(d, a_, b_, c_) \
    asm("fma.rn.f32x2 %0, %1, %2, %3;" : "=l"(d) : "l"(a_), "l"(b_), "l"(c_))
#define ADD2(d, a_, b_) \
    asm("add.rn.f32x2 %0, %1, %2;" : "=l"(d) : "l"(a_), "l"(b_))
#define PAIR_BAR(pid) \
    asm volatile("bar.sync %0, %1;" :: "r"((pid) + 1), "r"(64) : "memory")

__device__ __forceinline__ void cp16(unsigned smaddr, const void* g) {
    asm volatile("cp.async.cg.shared.global [%0], [%1], 16;" :: "r"(smaddr), "l"(g));
}

// ---------------- merged prep kernel ----------------
// blocks 0..1535   : Wc[f][n][k] + u reduction   (b = n*64 + f)
// blocks 1536..1559: bc[n][k] + v reduction
__global__ void prep(const float* __restrict__ Wp, const float* __restrict__ bp,
                     const float* __restrict__ W, const float* __restrict__ a) {
    int b = blockIdx.x;
    int k = threadIdx.x;          // 0..63
    float acc = 0.f;

    if (b < 1536) {
        int n = b >> 6, f = b & 63;
#pragma unroll 8
        for (int h = 0; h < 64; h++)
            acc = fmaf(Wp[f * 1536 + n * 64 + h], W[h * 64 + k], acc);
        g_Wc[f * 1536 + n * 64 + k] = acc;
    } else {
        int n = b - 1536;
#pragma unroll 8
        for (int h = 0; h < 64; h++)
            acc = fmaf(bp[n * 64 + h], W[h * 64 + k], acc);
        g_bc[n * 64 + k] = acc;
    }

    float p1 = acc * a[k];
    float p2 = acc * a[64 + k];
#pragma unroll
    for (int d = 16; d; d >>= 1) {
        p1 += __shfl_xor_sync(0xffffffffu, p1, d);
        p2 += __shfl_xor_sync(0xffffffffu, p2, d);
    }
    __shared__ float r1[2], r2[2];
    if ((k & 31) == 0) { r1[k >> 5] = p1; r2[k >> 5] = p2; }
    __syncthreads();
    if (k == 0) {
        if (b < 1536) {
            int n = b >> 6, f = b & 63;
            g_u[f * 48 + n]      = r1[0] + r1[1];
            g_u[f * 48 + 24 + n] = r2[0] + r2[1];
        } else {
            int n = b - 1536;
            g_v[n] = r1[0] + r1[1];
            g_v[24 + n] = r2[0] + r2[1];
        }
    }
}

// ---------------- main fused kernel ----------------
// 12 warps, 6 pairs. Pair p = w%6 owns rows 4p..4p+3 of this CTA's 24 rows.
// Warp p (hi=0) = n 0..11, warp p+6 (hi=1) = n 12..23.
__global__ __launch_bounds__(NTHREADS, 1)
void gat_main(const float* __restrict__ x, const int* __restrict__ adj,
              float* __restrict__ out) {
    extern __shared__ char smem[];
    float* s_wc   = (float*)smem;
    ull*   s_P    = (ull*)smem;                 // overlays Wc region in phase 2
    ull*   s_park = s_P + 6 * 600;              // 6 pairs x 768 ull (high partials)
    ull*   s_xd   = (ull*)(smem + OFF_XD);      // 64 x 26 ull, {x,x} pairs [f][row]
    float* s_u    = (float*)(smem + OFF_U);
    float* s_v    = (float*)(smem + OFF_V);
    unsigned* s_adjJ = (unsigned*)(smem + OFF_ADJJ);
    float* s_sse  = (float*)(smem + OFF_SSE);   // 6 pairs x 2 halves x 32
    float* s_rs   = (float*)(smem + OFF_RS);    // 6 pairs x 24
    unsigned* s_bad = (unsigned*)(smem + OFF_BAD);

    const int tid  = threadIdx.x;
    const int lane = tid & 31;
    const int w    = tid >> 5;
    const int pair = (w >= 6) ? (w - 6) : w;
    const int hi   = (w >= 6) ? 1 : 0;          // 0 = n 0..11, 1 = n 12..23
    const int nbase = hi * 12;
    const int rowbase = blockIdx.x * ROWS_PER_CTA;

    const unsigned swc0 = (unsigned)__cvta_generic_to_shared(s_wc);

    // prologue: stage f-block 0 of Wc (8 f-rows, 48 KB) into buffer 0
    for (int c = tid; c < 3072; c += NTHREADS) cp16(swc0 + c * 16, g_Wc + c * 4);
    asm volatile("cp.async.commit_group;");

    // stage x as duplicated {x,x} pairs: s_xd[f*26 + r]; clamp tail rows
    for (int i = tid; i < ROWS_PER_CTA * 64; i += NTHREADS) {
        int r = i >> 6, f = i & 63;
        int rr = rowbase + r; if (rr > TOTAL_ROWS - 1) rr = TOTAL_ROWS - 1;
        s_xd[f * 26 + r] = packdup(x[rr * 64 + f]);
    }
    for (int i = tid; i < 3072; i += NTHREADS) s_u[i] = g_u[i];
    if (tid < 48) s_v[tid] = g_v[tid];
    if (tid < 24) {
        unsigned b = 0;
        for (int i = 0; i < 24; i++) b |= (adj[i * 24 + tid] > 0 ? 1u : 0u) << i;
        s_adjJ[tid] = b;
    }
    // badrow bitmask (depends only on adj): bit i set if row i fully masked
    if (w == 0) {
        unsigned rowOr = 0;
        if (lane < 24)
            for (int j = 0; j < 24; j++) rowOr |= (adj[lane * 24 + j] > 0 ? 1u : 0u);
        unsigned bm = __ballot_sync(0xffffffffu, (lane < 24) && (rowOr == 0));
        if (lane == 0) s_bad[0] = bm;
    }

    // Wh accumulators: lane owns k = 2*lane, 2*lane+1; 4 rows x 12 n (this half)
    ull wh[4][12];
#pragma unroll
    for (int q = 0; q < 12; q++) {
        ull b = ((const ull*)g_bc)[(nbase + q) * 32 + lane];
        wh[0][q] = b; wh[1][q] = b; wh[2][q] = b; wh[3][q] = b;
    }

    __syncthreads();

    // ---------------- phase 1: Wh = x @ Wc + bc ----------------
    for (int fb = 0; fb < 8; fb++) {
        if (fb < 7) {
            unsigned dst = swc0 + (unsigned)(((fb + 1) & 1) * 49152);
            const float* src = g_Wc + (fb + 1) * 12288;
            for (int c = tid; c < 3072; c += NTHREADS) cp16(dst + c * 16, src + c * 4);
            asm volatile("cp.async.commit_group;");
            asm volatile("cp.async.wait_group 1;");
        } else {
            asm volatile("cp.async.wait_group 0;");
        }
        __syncthreads();

        const float* wct = s_wc + (fb & 1) * 12288;
#pragma unroll
        for (int ff = 0; ff < 8; ff++) {
            const ulonglong2* xp =
                (const ulonglong2*)(s_xd + (fb * 8 + ff) * 26 + 4 * pair);
            ulonglong2 xa = xp[0], xb = xp[1];
            const ull* wrow = ((const ull*)(wct + ff * 1536)) + nbase * 32 + lane;
#pragma unroll
            for (int g2 = 0; g2 < 3; g2++) {
                ull w2[4];
#pragma unroll
                for (int q = 0; q < 4; q++) w2[q] = wrow[(g2 * 4 + q) * 32];
#pragma unroll
                for (int q = 0; q < 4; q++) {
                    const int n = g2 * 4 + q;
                    FMA2(wh[0][n], w2[q], xa.x, wh[0][n]);
                    FMA2(wh[1][n], w2[q], xa.y, wh[1][n]);
                    FMA2(wh[2][n], w2[q], xb.x, wh[2][n]);
                    FMA2(wh[3][n], w2[q], xb.y, wh[3][n]);
                }
            }
        }
        __syncthreads();
    }

    // ---------------- phase 2: attention + aggregate ----------------
    const int ln = (lane < 24) ? lane : 0;
    const unsigned badmask = s_bad[0];
    const int isbad = (badmask >> ln) & 1;

    // f1/f2 for this pair's 4 rows, lane = node n (both warps compute)
    float f1[4], f2[4];
#pragma unroll
    for (int r = 0; r < 4; r++) { f1[r] = s_v[ln]; f2[r] = s_v[24 + ln]; }
#pragma unroll 4
    for (int f = 0; f < 64; f++) {
        float u1 = s_u[f * 48 + ln];
        float u2 = s_u[f * 48 + 24 + ln];
        const float* xr = (const float*)(s_xd + f * 26 + 4 * pair);
#pragma unroll
        for (int r = 0; r < 4; r++) {
            float xf = xr[2 * r];
            f1[r] = fmaf(xf, u1, f1[r]);
            f2[r] = fmaf(xf, u2, f2[r]);
        }
    }

    ull* Pw = s_P + pair * 600;          // 24 x 25 ull per pair
    ull* Pt = s_park + pair * 768;       // 24 x 32 ull (high warp's partials)
    const float inv24 = 1.0f / 24.0f;

    for (int r = 0; r < 4; r++) {
        // ---- stage A: both warps, own j-half; lanes = i ----
        {
            float sse = 0.f;
            const float f1v = f1[r], f2v = f2[r];
#pragma unroll
            for (int jq = 0; jq < 12; jq++) {
                const int j = nbase + jq;
                float f2j = __shfl_sync(0xffffffffu, f2v, j);
                float e = f1v + f2j;
                e = (e > 0.f) ? e : 0.2f * e;          // LeakyReLU
                unsigned bits = s_adjJ[j];             // uniform
                float p = isbad ? 1.f
                                : (((bits >> lane) & 1u) ? __expf(e) : 0.f);
                sse += p;
                if (lane < 24) Pw[lane * 25 + j] = packdup(p);
            }
            if (lane < 24) s_sse[pair * 64 + hi * 32 + lane] = sse;
        }
        PAIR_BAR(pair);                                // probs + sse halves ready

        if (hi) {
            // ---- stage B (high): partial over j = 12..23 for all i, park ----
            for (int i = 0; i < 24; i++) {
                const ull* Prow = Pw + i * 25 + 12;
                ull hp0 = 0ULL, hp1 = 0ULL;
#pragma unroll
                for (int q = 0; q < 6; q++)  { FMA2(hp0, Prow[q], wh[r][q], hp0); }
#pragma unroll
                for (int q = 6; q < 12; q++) { FMA2(hp1, Prow[q], wh[r][q], hp1); }
                ull hp; ADD2(hp, hp0, hp1);
                Pt[i * 32 + lane] = hp;
            }
        } else {
            // rs from both sse halves (only low needs it)
            if (lane < 24) {
                float s = s_sse[pair * 64 + lane] + s_sse[pair * 64 + 32 + lane];
                s_rs[pair * 24 + lane] = __fdividef(1.f, s);
            }
        }
        PAIR_BAR(pair);                                // partials + rs ready

        if (!hi) {
            // ---- combine (low): own partial + parked, scale, ELU, mean ----
            float acc0 = 0.f, acc1 = 0.f;
            for (int i = 0; i < 24; i++) {
                const ull* Prow = Pw + i * 25;
                ull hp0 = 0ULL, hp1 = 0ULL;
#pragma unroll
                for (int q = 0; q < 6; q++)  { FMA2(hp0, Prow[q], wh[r][q], hp0); }
#pragma unroll
                for (int q = 6; q < 12; q++) { FMA2(hp1, Prow[q], wh[r][q], hp1); }
                ull oth = Pt[i * 32 + lane];
                ull hps, hp;
                ADD2(hps, hp0, hp1);
                ADD2(hp, hps, oth);
                float rsv = s_rs[pair * 24 + i];       // uniform
                float hx = __uint_as_float((unsigned)hp) * rsv;
                float hy = __uint_as_float((unsigned)(hp >> 32)) * rsv;
                acc0 += (hx > 0.f) ? hx : __expf(hx) - 1.f;   // ELU
                acc1 += (hy > 0.f) ? hy : __expf(hy) - 1.f;
            }
            const int row = rowbase + 4 * pair + r;
            if (row < TOTAL_ROWS) {
                float2 o; o.x = acc0 * inv24; o.y = acc1 * inv24;
                ((float2*)out)[row * 32 + lane] = o;
            }
        }
        PAIR_BAR(pair);                                // protect Pw/Pt for next r
    }
}

// ---------------- launch ----------------
extern "C" void kernel_launch(void* const* d_in, const int* in_sizes, int n_in,
                              void* d_out, int out_size) {
    (void)in_sizes; (void)n_in; (void)out_size;
    const float* x   = (const float*)d_in[0];
    const int*   adj = (const int*)d_in[1];
    const float* Wp  = (const float*)d_in[2];
    const float* bp  = (const float*)d_in[3];
    const float* W   = (const float*)d_in[4];
    const float* a   = (const float*)d_in[5];
    float* out = (float*)d_out;

    cudaFuncSetAttribute(gat_main, cudaFuncAttributeMaxDynamicSharedMemorySize,
                         SMEM_BYTES);

    prep<<<1560, 64>>>(Wp, bp, W, a);
    gat_main<<<GRID, NTHREADS, SMEM_BYTES>>>(x, adj, out);
}

// round 14
// speedup vs baseline: 5.9257x; 1.7242x over previous
#include <cuda_runtime.h>

typedef unsigned long long ull;

// ---------------- device-global buffers ----------------
__device__ float g_Wc[64 * 1536];     // [f][col], col = n*64+k
__device__ float g_u[64 * 48];        // [f][n], [f][24+n]
__device__ float g_v[48];
__device__ float g_bc[24 * 64];       // bc[n][k] -> linear col
__device__ float g_Wh[32768 * 1536];  // Wh = x @ Wc + bc   (201 MB scratch)

// ---------------- helpers ----------------
__device__ __forceinline__ ull packdup(float v) {
    ull r; asm("mov.b64 %0, {%1, %1};" : "=l"(r) : "f"(v)); return r;
}
#define FMA2(d, a_, b_, c_) \
    asm("fma.rn.f32x2 %0, %1, %2, %3;" : "=l"(d) : "l"(a_), "l"(b_), "l"(c_))
#define ADD2(d, a_, b_) \
    asm("add.rn.f32x2 %0, %1, %2;" : "=l"(d) : "l"(a_), "l"(b_))

// ---------------- prep kernel ----------------
// blocks 0..1535   : Wc[f][n][k] + u reduction   (b = n*64 + f)
// blocks 1536..1559: bc[n][k] + v reduction
__global__ void prep(const float* __restrict__ Wp, const float* __restrict__ bp,
                     const float* __restrict__ W, const float* __restrict__ a) {
    int b = blockIdx.x;
    int k = threadIdx.x;          // 0..63
    float acc = 0.f;

    if (b < 1536) {
        int n = b >> 6, f = b & 63;
#pragma unroll 8
        for (int h = 0; h < 64; h++)
            acc = fmaf(Wp[f * 1536 + n * 64 + h], W[h * 64 + k], acc);
        g_Wc[f * 1536 + n * 64 + k] = acc;
    } else {
        int n = b - 1536;
#pragma unroll 8
        for (int h = 0; h < 64; h++)
            acc = fmaf(bp[n * 64 + h], W[h * 64 + k], acc);
        g_bc[n * 64 + k] = acc;
    }

    float p1 = acc * a[k];
    float p2 = acc * a[64 + k];
#pragma unroll
    for (int d = 16; d; d >>= 1) {
        p1 += __shfl_xor_sync(0xffffffffu, p1, d);
        p2 += __shfl_xor_sync(0xffffffffu, p2, d);
    }
    __shared__ float r1[2], r2[2];
    if ((k & 31) == 0) { r1[k >> 5] = p1; r2[k >> 5] = p2; }
    __syncthreads();
    if (k == 0) {
        if (b < 1536) {
            int n = b >> 6, f = b & 63;
            g_u[f * 48 + n]      = r1[0] + r1[1];
            g_u[f * 48 + 24 + n] = r2[0] + r2[1];
        } else {
            int n = b - 1536;
            g_v[n] = r1[0] + r1[1];
            g_v[24 + n] = r2[0] + r2[1];
        }
    }
}

// ---------------- GEMM kernel: g_Wh = x @ g_Wc + g_bc ----------------
// C [32768,1536] = A [32768,64] @ B [64,1536].  Tile 128x128, K=64 whole.
// 256 thr: tx = tid&15 (cols), ty = tid>>4 (rows). Thread tile: 8 rows x 4 col-pairs,
// col-pair index c2 = cp*16 + tx  (strided for coalesced STG).
#define XD_STRIDE 129                           /* ull stride, bank-spread */
#define GEMM_OFF_WT (64 * XD_STRIDE * 8)        /* 66048 */
#define GEMM_SMEM (GEMM_OFF_WT + 64 * 64 * 8)   /* + 32768 = 98816 */

__global__ __launch_bounds__(256, 2)
void gemm_wh(const float* __restrict__ x) {
    extern __shared__ char smem[];
    ull* xd = (ull*)smem;                        // [k][row] dup pairs, stride 129
    ull* wt = (ull*)(smem + GEMM_OFF_WT);        // [k][c2]  Wc col-pairs

    const int tid = threadIdx.x;
    const int tx = tid & 15, ty = tid >> 4;
    const int rowbase = blockIdx.x * 128;
    const int colbase = blockIdx.y * 128;

    // stage x tile: 128 rows x 64 k, duplicated
    {
        int i = tid;                             // 2048 float4 loads / 256 thr = 8
#pragma unroll
        for (int it = 0; it < 8; it++, i += 256) {
            int r = i >> 4, kq = i & 15;
            float4 v = *(const float4*)(x + (rowbase + r) * 64 + kq * 4);
            xd[(kq * 4 + 0) * XD_STRIDE + r] = packdup(v.x);
            xd[(kq * 4 + 1) * XD_STRIDE + r] = packdup(v.y);
            xd[(kq * 4 + 2) * XD_STRIDE + r] = packdup(v.z);
            xd[(kq * 4 + 3) * XD_STRIDE + r] = packdup(v.w);
        }
    }
    // stage Wc tile: 64 k x 64 col-pairs
    {
        int i = tid;                             // 4096 ull / 256 = 16
#pragma unroll
        for (int it = 0; it < 16; it++, i += 256) {
            int k = i >> 6, c2 = i & 63;
            wt[k * 64 + c2] = *(const ull*)(g_Wc + k * 1536 + colbase + 2 * c2);
        }
    }
    __syncthreads();

    ull acc[8][4];
#pragma unroll
    for (int r = 0; r < 8; r++)
#pragma unroll
        for (int cp = 0; cp < 4; cp++) acc[r][cp] = 0ULL;

    const ull* xrow = xd + ty * 8;
    const ull* wrow = wt + tx;

#pragma unroll 4
    for (int k = 0; k < 64; k++) {
        ull xv[8], wv[4];
#pragma unroll
        for (int r = 0; r < 8; r++) xv[r] = xrow[k * XD_STRIDE + r];
#pragma unroll
        for (int cp = 0; cp < 4; cp++) wv[cp] = wrow[k * 64 + cp * 16];
#pragma unroll
        for (int r = 0; r < 8; r++)
#pragma unroll
            for (int cp = 0; cp < 4; cp++)
                FMA2(acc[r][cp], wv[cp], xv[r], acc[r][cp]);
    }

    // epilogue: + bc, store
    const ull* gb = ((const ull*)g_bc) + (colbase >> 1) + tx;
#pragma unroll
    for (int cp = 0; cp < 4; cp++) {
        ull b = gb[cp * 16];
#pragma unroll
        for (int r = 0; r < 8; r++) ADD2(acc[r][cp], acc[r][cp], b);
    }
#pragma unroll
    for (int r = 0; r < 8; r++) {
        float* orow = g_Wh + (size_t)(rowbase + ty * 8 + r) * 1536 + colbase;
#pragma unroll
        for (int cp = 0; cp < 4; cp++)
            *(ull*)(orow + 2 * (cp * 16 + tx)) = acc[r][cp];
    }
}

// ---------------- attention kernel ----------------
// 256 thr, 8 warps, warp = one row. grid 4096.
#define AT_OFF_U   38400                 /* after 8 x 600 ull P scratch */
#define AT_OFF_X   (AT_OFF_U + 12288)    /* 50688 */
#define AT_OFF_V   (AT_OFF_X + 2048)     /* 52736 */
#define AT_OFF_ADJ (AT_OFF_V + 192)      /* 52928 */
#define AT_OFF_BAD (AT_OFF_ADJ + 96)     /* 53024 */
#define AT_SMEM    (AT_OFF_BAD + 32)     /* 53056 */

__global__ __launch_bounds__(256, 2)
void attn(const float* __restrict__ x, const int* __restrict__ adj,
          float* __restrict__ out) {
    extern __shared__ char smem[];
    ull*   s_P   = (ull*)smem;                      // 8 warps x 600
    float* s_u   = (float*)(smem + AT_OFF_U);
    float* s_x   = (float*)(smem + AT_OFF_X);       // 8 rows x 64
    float* s_v   = (float*)(smem + AT_OFF_V);
    unsigned* s_adjJ = (unsigned*)(smem + AT_OFF_ADJ);
    unsigned* s_bad  = (unsigned*)(smem + AT_OFF_BAD);

    const int tid  = threadIdx.x;
    const int lane = tid & 31;
    const int w    = tid >> 5;
    const int row  = blockIdx.x * 8 + w;

    // ---- CTA staging ----
    for (int i = tid; i < 3072; i += 256) s_u[i] = g_u[i];
    if (tid < 48) s_v[tid] = g_v[tid];
    if (tid < 24) {
        unsigned b = 0;
        for (int i = 0; i < 24; i++) b |= (adj[i * 24 + tid] > 0 ? 1u : 0u) << i;
        s_adjJ[tid] = b;
    }
    if (w == 0) {
        unsigned rowOr = 0;
        if (lane < 24)
            for (int j = 0; j < 24; j++) rowOr |= (adj[lane * 24 + j] > 0 ? 1u : 0u);
        unsigned bm = __ballot_sync(0xffffffffu, (lane < 24) && (rowOr == 0));
        if (lane == 0) s_bad[0] = bm;
    }
    // this warp's x row -> smem
    {
        float2 v = *(const float2*)(x + row * 64 + 2 * lane);
        *(float2*)(s_x + w * 64 + 2 * lane) = v;
    }

    // ---- load Wh rows for this sample: wh[n], lane = k-pair (MLP-friendly) ----
    ull wh[24];
    {
        const ull* whp = ((const ull*)(g_Wh + (size_t)row * 1536)) + lane;
#pragma unroll
        for (int n = 0; n < 24; n++) wh[n] = whp[n * 32];
    }
    __syncthreads();

    const int ln = (lane < 24) ? lane : 0;
    const int isbad = (s_bad[0] >> ln) & 1;

    // ---- f1/f2 (lane = node) ----
    float f1 = s_v[ln], f2 = s_v[24 + ln];
#pragma unroll 8
    for (int f = 0; f < 64; f++) {
        float xf = s_x[w * 64 + f];                // broadcast
        f1 = fmaf(xf, s_u[f * 48 + ln], f1);
        f2 = fmaf(xf, s_u[f * 48 + 24 + ln], f2);
    }

    // ---- stage A: unnormalized probs (lanes = i, loop j) ----
    ull* Pw = s_P + w * 600;                        // 24 x 25 ull
    float sse = 0.f;
#pragma unroll 6
    for (int j = 0; j < 24; j++) {
        float f2j = __shfl_sync(0xffffffffu, f2, j);
        float e = f1 + f2j;
        e = (e > 0.f) ? e : 0.2f * e;               // LeakyReLU
        unsigned bits = s_adjJ[j];                  // uniform
        float p = isbad ? 1.f : (((bits >> lane) & 1u) ? __expf(e) : 0.f);
        sse += p;
        if (lane < 24) Pw[lane * 25 + j] = packdup(p);
    }
    float rsinv = __fdividef(1.f, sse);             // valid for lanes < 24
    __syncwarp();

    // ---- stage B: h' = attn @ Wh (lanes = k-pair, loop i) ----
    float acc0 = 0.f, acc1 = 0.f;
    const float inv24 = 1.0f / 24.0f;
    for (int i = 0; i < 24; i++) {
        const ull* Prow = Pw + i * 25;
        ull hp0 = 0ULL, hp1 = 0ULL;
#pragma unroll
        for (int q = 0; q < 12; q++)  { FMA2(hp0, Prow[q],      wh[q],      hp0); }
#pragma unroll
        for (int q = 0; q < 12; q++)  { FMA2(hp1, Prow[12 + q], wh[12 + q], hp1); }
        ull hp; ADD2(hp, hp0, hp1);
        float rsv = __shfl_sync(0xffffffffu, rsinv, i);
        float hx = __uint_as_float((unsigned)hp) * rsv;
        float hy = __uint_as_float((unsigned)(hp >> 32)) * rsv;
        acc0 += (hx > 0.f) ? hx : __expf(hx) - 1.f; // ELU
        acc1 += (hy > 0.f) ? hy : __expf(hy) - 1.f;
    }

    float2 o; o.x = acc0 * inv24; o.y = acc1 * inv24;
    ((float2*)out)[row * 32 + lane] = o;
}

// ---------------- launch ----------------
extern "C" void kernel_launch(void* const* d_in, const int* in_sizes, int n_in,
                              void* d_out, int out_size) {
    (void)in_sizes; (void)n_in; (void)out_size;
    const float* x   = (const float*)d_in[0];
    const int*   adj = (const int*)d_in[1];
    const float* Wp  = (const float*)d_in[2];
    const float* bp  = (const float*)d_in[3];
    const float* W   = (const float*)d_in[4];
    const float* a   = (const float*)d_in[5];
    float* out = (float*)d_out;

    cudaFuncSetAttribute(gemm_wh, cudaFuncAttributeMaxDynamicSharedMemorySize,
                         GEMM_SMEM);
    cudaFuncSetAttribute(attn, cudaFuncAttributeMaxDynamicSharedMemorySize,
                         AT_SMEM);

    prep<<<1560, 64>>>(Wp, bp, W, a);
    gemm_wh<<<dim3(256, 12), 256, GEMM_SMEM>>>(x);
    attn<<<4096, 256, AT_SMEM>>>(x, adj, out);
}